// round 5
// baseline (speedup 1.0000x reference)
#include <cuda_runtime.h>
#include <math.h>

#define NCH  31
#define NREG 9
#define RPB  16
#define TPB  256
#define GX   (2048 / RPB)
#define NBLK (GX * NCH)
#define SCRATCH_N (1 + NREG * NCH * 7)

// scratch[0] = global target sum; per (r,c): {St1, St3, Sxt3, Syt3, Sp3, Sxp3, Syp3}
__device__ double g_scratch[SCRATCH_N];
__device__ unsigned int g_cnt = 0;

__device__ __forceinline__ float wsumf(float v) {
#pragma unroll
    for (int o = 16; o; o >>= 1) v += __shfl_down_sync(0xffffffffu, v, o);
    return v;
}
__device__ __forceinline__ double wsumd(double v) {
#pragma unroll
    for (int o = 16; o; o >>= 1) v += __shfl_down_sync(0xffffffffu, v, o);
    return v;
}

__device__ __forceinline__ void classify(int j, int& cb, float& offb) {
    cb = -1; int bxs = 0;
    if      (j >= 50  && j < 150) { cb = 0; bxs = 50;  }
    else if (j >= 250 && j < 350) { cb = 1; bxs = 250; }
    else if (j >= 375 && j < 475) { cb = 2; bxs = 375; }
    offb = (float)((j - bxs) * 4);
}

__device__ __forceinline__ void accum_band(
    const float4 t, const float i0f, const float offb, float* A) {
    const float s1 = (t.x + t.y) + (t.z + t.w);
    A[0] += s1;
    const float a3 = t.x*t.x*t.x, b3 = t.y*t.y*t.y;
    const float c3 = t.z*t.z*t.z, d3 = t.w*t.w*t.w;
    const float s3 = (a3 + b3) + (c3 + d3);
    A[1] += s3;
    A[2] = fmaf(i0f, s3, A[2]);
    A[3] += fmaf(offb, s3, b3 + 2.f*c3 + 3.f*d3);
}

__device__ __forceinline__ void accum_band_p(
    const float4 p, const float i0f, const float offb, float* A) {
    const float e3 = p.x*p.x*p.x, f3 = p.y*p.y*p.y;
    const float g3 = p.z*p.z*p.z, h3 = p.w*p.w*p.w;
    const float sp = (e3 + f3) + (g3 + h3);
    A[4] += sp;
    A[5] = fmaf(i0f, sp, A[5]);
    A[6] += fmaf(offb, sp, f3 + 2.f*g3 + 3.f*h3);
}

__global__ __launch_bounds__(TPB, 4) void coml_kernel(
    const float* __restrict__ pred, const float* __restrict__ targ,
    float* __restrict__ out) {
    const int ch  = blockIdx.y;
    const int y0  = blockIdx.x * RPB;
    const int tid = threadIdx.x;
    const int lane = tid & 31, wid = tid >> 5;

    // block row-band intersection (a 16-row group overlaps at most one band)
    int rbm = -1, bs = 0;
    if      (y0 < 600  && y0 + RPB > 200)  { rbm = 0; bs = 200;  }
    else if (y0 < 1400 && y0 + RPB > 1000) { rbm = 1; bs = 1000; }
    else if (y0 < 1900 && y0 + RPB > 1500) { rbm = 2; bs = 1500; }
    int rlo = 0, rhi = 0;
    if (rbm >= 0) { rlo = max(0, bs - y0); rhi = min(RPB, bs + 400 - y0); }

    // this thread's two float4 slots
    const int j0 = tid * 2, j1 = tid * 2 + 1;
    int cbA, cbB; float ofA, ofB;
    classify(j0, cbA, ofA);
    classify(j1, cbB, ofB);

    const size_t base4 = (((size_t)ch << 22) + ((size_t)y0 << 11)) >> 2;
    const float4* tp = (const float4*)targ + base4;
    const float4* pp = (const float4*)pred + base4;

    float gA = 0.f, gB = 0.f;
    float SA[7], SB[7];
#pragma unroll
    for (int k = 0; k < 7; k++) { SA[k] = 0.f; SB[k] = 0.f; }

    if (rbm < 0) {
#pragma unroll
        for (int rr = 0; rr < RPB; rr++) {
            const float4 a = tp[rr * 512 + j0];
            const float4 b = tp[rr * 512 + j1];
            gA += (a.x + a.y) + (a.z + a.w);
            gB += (b.x + b.y) + (b.z + b.w);
        }
    } else {
        for (int rr = 0; rr < rlo; rr++) {
            const float4 a = tp[rr * 512 + j0];
            const float4 b = tp[rr * 512 + j1];
            gA += (a.x + a.y) + (a.z + a.w);
            gB += (b.x + b.y) + (b.z + b.w);
        }
#pragma unroll 4
        for (int rr = rlo; rr < rhi; rr++) {
            const float4 a = tp[rr * 512 + j0];
            const float4 b = tp[rr * 512 + j1];
            const float i0f = (float)(y0 + rr - bs);
            gA += (a.x + a.y) + (a.z + a.w);
            gB += (b.x + b.y) + (b.z + b.w);
            if (cbA >= 0) {
                accum_band(a, i0f, ofA, SA);
                accum_band_p(pp[rr * 512 + j0], i0f, ofA, SA);
            }
            if (cbB >= 0) {
                accum_band(b, i0f, ofB, SB);
                accum_band_p(pp[rr * 512 + j1], i0f, ofB, SB);
            }
        }
        for (int rr = rhi; rr < RPB; rr++) {
            const float4 a = tp[rr * 512 + j0];
            const float4 b = tp[rr * 512 + j1];
            gA += (a.x + a.y) + (a.z + a.w);
            gB += (b.x + b.y) + (b.z + b.w);
        }
    }

    // ---- block reduction: stat-major 512-wide staging, contiguous ranges ----
    __shared__ float sh[8 * 512];
    sh[0*512 + j0] = gA;     sh[0*512 + j1] = gB;
#pragma unroll
    for (int k = 0; k < 7; k++) {
        sh[(k+1)*512 + j0] = SA[k];
        sh[(k+1)*512 + j1] = SB[k];
    }
    __syncthreads();

    for (int item = wid; item < 22; item += 8) {
        int k, lo, hi, b = -1;
        if (item == 0) { k = 0; lo = 0; hi = 512; }
        else {
            b = (item - 1) / 7;
            const int s = (item - 1) % 7;
            k = 1 + s;
            lo = (b == 0) ? 50 : (b == 1) ? 250 : 375;
            hi = lo + 100;
        }
        float s = 0.f;
        for (int i = lo + lane; i < hi; i += 32) s += sh[k * 512 + i];
        s = wsumf(s);
        if (lane == 0) {
            if (item == 0) atomicAdd(&g_scratch[0], (double)s);
            else if (rbm >= 0 && rhi > rlo) {
                const int st = (item - 1) % 7;
                const int r = rbm * 3 + b;
                atomicAdd(&g_scratch[1 + (r * NCH + ch) * 7 + st], (double)s);
            }
        }
    }

    // ---- last block computes the loss and resets scratch ----
    __threadfence();
    __shared__ unsigned int ticket;
    __syncthreads();
    if (tid == 0) ticket = atomicAdd(&g_cnt, 1u);
    __syncthreads();
    if (ticket == NBLK - 1) {
        __threadfence();
        volatile double* vs = g_scratch;
        const double mean_t = vs[0] / ((double)NCH * 2048.0 * 2048.0);
        double term = 0.0;
        for (int i = tid; i < NREG * NCH; i += TPB) {
            const int r = i / NCH;
            const double St1  = vs[1 + i*7 + 0], St3  = vs[1 + i*7 + 1];
            const double Sxt3 = vs[1 + i*7 + 2], Syt3 = vs[1 + i*7 + 3];
            const double Sp3  = vs[1 + i*7 + 4], Sxp3 = vs[1 + i*7 + 5];
            const double Syp3 = vs[1 + i*7 + 6];
            const double cxt = (St3 != 0.0) ? Sxt3 / St3 : 0.0;
            const double cyt = (St3 != 0.0) ? Syt3 / St3 : 0.0;
            const double cxp = (Sp3 != 0.0) ? Sxp3 / Sp3 : 0.0;
            const double cyp = (Sp3 != 0.0) ? Syp3 / Sp3 : 0.0;
            const double dx = cxp - cxt, dy = cyp - cyt;
            double t = sqrt(dx * dx + dy * dy) * ((St1 / 160000.0) / mean_t);
            if (r == 4) t *= 5.0;  // fundamental region weight
            term += t;
        }
        term = wsumd(term);
        __shared__ double wpart[8];
        if (lane == 0) wpart[wid] = term;
        __syncthreads();
        if (tid == 0) {
            double s = 0.0;
#pragma unroll
            for (int w = 0; w < 8; w++) s += wpart[w];
            out[0] = (float)(s / (double)(NREG * NCH));
            g_cnt = 0;
        }
        for (int i = tid; i < SCRATCH_N; i += TPB) g_scratch[i] = 0.0;
    }
}

extern "C" void kernel_launch(void* const* d_in, const int* in_sizes, int n_in,
                              void* d_out, int out_size) {
    const float* pred = (const float*)d_in[0];
    const float* targ = (const float*)d_in[1];
    dim3 grid(GX, NCH);
    coml_kernel<<<grid, TPB>>>(pred, targ, (float*)d_out);
}

// round 6
// speedup vs baseline: 1.0876x; 1.0876x over previous
#include <cuda_runtime.h>
#include <math.h>

#define NCH   31
#define NREG  9
#define RPB   16
#define TPB   512
#define NBAND 2418            // 78 band groups * 31 channels
#define NSTRM 1550            // 50 stream groups * 31 channels
#define NTILES (NBAND + NSTRM)
#define PGRID 444             // persistent blocks (3 per SM on 148 SMs)
#define SCRATCH_N (1 + NREG * NCH * 7)

// scratch[0] = global target sum; per (r,c): {St1, St3, Sxt3, Syt3, Sp3, Sxp3, Syp3}
__device__ double g_scratch[SCRATCH_N];
__device__ unsigned int g_cnt  = 0;
__device__ unsigned int g_tile = 0;

__device__ __forceinline__ float wsumf(float v) {
#pragma unroll
    for (int o = 16; o; o >>= 1) v += __shfl_down_sync(0xffffffffu, v, o);
    return v;
}
__device__ __forceinline__ double wsumd(double v) {
#pragma unroll
    for (int o = 16; o; o >>= 1) v += __shfl_down_sync(0xffffffffu, v, o);
    return v;
}

__global__ __launch_bounds__(TPB, 3) void coml_kernel(
    const float* __restrict__ pred, const float* __restrict__ targ,
    float* __restrict__ out) {
    const int tid  = threadIdx.x;
    const int lane = tid & 31, wid = tid >> 5;

    // thread col-band (float4 index == tid; all edges multiples of 4)
    int cb = -1, bxs = 0;
    if      (tid >= 50  && tid < 150) { cb = 0; bxs = 50;  }
    else if (tid >= 250 && tid < 350) { cb = 1; bxs = 250; }
    else if (tid >= 375 && tid < 475) { cb = 2; bxs = 375; }
    const float offb = (float)((tid - bxs) * 4);

    float gsum = 0.f;             // carried across ALL tiles this CTA handles
    __shared__ int   sh_tile;
    __shared__ float sh[7 * 512];

    for (;;) {
        if (tid == 0) sh_tile = (int)atomicAdd(&g_tile, 1u);
        __syncthreads();
        const int t = sh_tile;
        __syncthreads();
        if (t >= NTILES) break;

        if (t < NBAND) {
            // ---------- band tile ----------
            const int ch = t / 78, i = t % 78;
            int rbm, g, bs;
            if      (i < 26) { rbm = 0; g = 12 + i; bs = 200;  }
            else if (i < 52) { rbm = 1; g = 36 + i; bs = 1000; }  // 62+(i-26)
            else             { rbm = 2; g = 41 + i; bs = 1500; }  // 93+(i-52)
            const int y0  = g * RPB;
            const int rlo = max(0, bs - y0);
            const int rhi = min(RPB, bs + 400 - y0);

            const size_t base4 = (((size_t)ch << 22) + ((size_t)y0 << 11)) >> 2;
            const float4* tp = (const float4*)targ + base4 + tid;
            const float4* pp = (const float4*)pred + base4 + tid;

            float SA[7];
#pragma unroll
            for (int k = 0; k < 7; k++) SA[k] = 0.f;

            for (int rr = 0; rr < rlo; rr++) {
                const float4 a = __ldcs(&tp[rr * 512]);
                gsum += (a.x + a.y) + (a.z + a.w);
            }
#pragma unroll 4
            for (int rr = rlo; rr < rhi; rr++) {
                const float4 v = __ldcs(&tp[rr * 512]);
                const float s1 = (v.x + v.y) + (v.z + v.w);
                gsum += s1;
                if (cb >= 0) {
                    const float i0f = (float)(y0 + rr - bs);
                    SA[0] += s1;
                    const float a3 = v.x*v.x*v.x, b3 = v.y*v.y*v.y;
                    const float c3 = v.z*v.z*v.z, d3 = v.w*v.w*v.w;
                    const float s3 = (a3 + b3) + (c3 + d3);
                    SA[1] += s3;
                    SA[2] = fmaf(i0f, s3, SA[2]);
                    SA[3] += fmaf(offb, s3, b3 + 2.f*c3 + 3.f*d3);
                    const float4 p = __ldcs(&pp[rr * 512]);
                    const float e3 = p.x*p.x*p.x, f3 = p.y*p.y*p.y;
                    const float g3 = p.z*p.z*p.z, h3 = p.w*p.w*p.w;
                    const float sp = (e3 + f3) + (g3 + h3);
                    SA[4] += sp;
                    SA[5] = fmaf(i0f, sp, SA[5]);
                    SA[6] += fmaf(offb, sp, f3 + 2.f*g3 + 3.f*h3);
                }
            }
            for (int rr = rhi; rr < RPB; rr++) {
                const float4 a = __ldcs(&tp[rr * 512]);
                gsum += (a.x + a.y) + (a.z + a.w);
            }

            // ---- band epilogue: 7 stats, 21 contiguous range sums ----
#pragma unroll
            for (int k = 0; k < 7; k++) sh[k * 512 + tid] = SA[k];
            __syncthreads();
            for (int item = wid; item < 21; item += 16) {
                const int b  = item / 7, st = item % 7;
                const int lo = (b == 0) ? 50 : (b == 1) ? 250 : 375;
                float s = 0.f;
#pragma unroll
                for (int u = 0; u < 4; u++) s += sh[st * 512 + lo + lane + u * 32];
                s += sh[st * 512 + lo + ((lane + 128) & 127) + ((lane < 4) ? 0 : 0)] * 0.f; // (no-op keep simple)
                // 100 elements: lanes 0..31 strided -> 3 full strides + 4 extra
                s += (lane < 4) ? sh[st * 512 + lo + 96 + lane] * 0.f : 0.f; // placeholder
                s = 0.f;
                for (int idx = lo + lane; idx < lo + 100; idx += 32) s += sh[st * 512 + idx];
                s = wsumf(s);
                if (lane == 0) {
                    const int r = rbm * 3 + b;
                    atomicAdd(&g_scratch[1 + (r * NCH + ch) * 7 + st], (double)s);
                }
            }
        } else {
            // ---------- stream tile: gsum only, no epilogue ----------
            const int s2 = t - NBAND;
            const int ch = s2 / 50, i = s2 % 50;
            int g;
            if      (i < 12) g = i;
            else if (i < 36) g = 26 + i;   // 38+(i-12)
            else if (i < 41) g = 52 + i;   // 88+(i-36)
            else             g = 78 + i;   // 119+(i-41)
            const size_t base4 = (((size_t)ch << 22) + ((size_t)(g * RPB) << 11)) >> 2;
            const float4* tp = (const float4*)targ + base4 + tid;
            float g0 = 0.f, g1 = 0.f;
#pragma unroll
            for (int rr = 0; rr < RPB; rr += 2) {
                const float4 a = __ldcs(&tp[rr * 512]);
                const float4 b = __ldcs(&tp[(rr + 1) * 512]);
                g0 += (a.x + a.y) + (a.z + a.w);
                g1 += (b.x + b.y) + (b.z + b.w);
            }
            gsum += g0 + g1;
        }
    }

    // ---- one gsum flush per CTA ----
    {
        float v = wsumf(gsum);
        __shared__ float wg[16];
        if (lane == 0) wg[wid] = v;
        __syncthreads();
        if (tid == 0) {
            float s = 0.f;
#pragma unroll
            for (int w = 0; w < 16; w++) s += wg[w];
            atomicAdd(&g_scratch[0], (double)s);
        }
    }

    // ---- last CTA computes the loss and resets state ----
    __threadfence();
    __shared__ unsigned int ticket;
    __syncthreads();
    if (tid == 0) ticket = atomicAdd(&g_cnt, 1u);
    __syncthreads();
    if (ticket == PGRID - 1) {
        __threadfence();
        volatile double* vs = g_scratch;
        const double mean_t = vs[0] / ((double)NCH * 2048.0 * 2048.0);
        double term = 0.0;
        if (tid < NREG * NCH) {
            const int r = tid / NCH;
            const double St1  = vs[1 + tid*7 + 0], St3  = vs[1 + tid*7 + 1];
            const double Sxt3 = vs[1 + tid*7 + 2], Syt3 = vs[1 + tid*7 + 3];
            const double Sp3  = vs[1 + tid*7 + 4], Sxp3 = vs[1 + tid*7 + 5];
            const double Syp3 = vs[1 + tid*7 + 6];
            const double cxt = (St3 != 0.0) ? Sxt3 / St3 : 0.0;
            const double cyt = (St3 != 0.0) ? Syt3 / St3 : 0.0;
            const double cxp = (Sp3 != 0.0) ? Sxp3 / Sp3 : 0.0;
            const double cyp = (Sp3 != 0.0) ? Syp3 / Sp3 : 0.0;
            const double dx = cxp - cxt, dy = cyp - cyt;
            term = sqrt(dx * dx + dy * dy) * ((St1 / 160000.0) / mean_t);
            if (r == 4) term *= 5.0;  // fundamental region weight
        }
        term = wsumd(term);
        __shared__ double wpart[16];
        if (lane == 0) wpart[wid] = term;
        __syncthreads();
        if (tid == 0) {
            double s = 0.0;
#pragma unroll
            for (int w = 0; w < 16; w++) s += wpart[w];
            out[0] = (float)(s / (double)(NREG * NCH));
            g_cnt  = 0;
            g_tile = 0;
        }
        for (int i = tid; i < SCRATCH_N; i += TPB) g_scratch[i] = 0.0;
    }
}

extern "C" void kernel_launch(void* const* d_in, const int* in_sizes, int n_in,
                              void* d_out, int out_size) {
    const float* pred = (const float*)d_in[0];
    const float* targ = (const float*)d_in[1];
    coml_kernel<<<PGRID, TPB>>>(pred, targ, (float*)d_out);
}